// round 15
// baseline (speedup 1.0000x reference)
#include <cuda_runtime.h>
#include <cuda_bf16.h>

#define GS 32
#define NN 16
#define SLICES 8
#define ATOM_TYPE 6

// Single MUFU EX2 regardless of compile flags.
__device__ __forceinline__ float ex2(float x) {
    float r;
    asm("ex2.approx.ftz.f32 %0, %1;" : "=f"(r) : "f"(x));
    return r;
}

// Streaming 128-bit store (evict-first: output is write-once).
__device__ __forceinline__ void stg_cs(float* p, float4 v) {
    asm volatile("st.global.cs.v4.f32 [%0], {%1,%2,%3,%4};"
                 :: "l"(p), "f"(v.x), "f"(v.y), "f"(v.z), "f"(v.w));
}

// out[b,a,i,j,k] = sum_{n: an[a,n]==6} exp(c*||grid - dv||^2), c = -0.5/sigma^2.
// Separable Gaussian on a UNIFORM grid => geometric ratio recurrence.
// dv rows live in the register file (lane l holds row l), broadcast into the
// mask loop via shfl -> the mask loop has NO memory ops. Per-thread work is
// unchanged from R14 champion (32 outputs); blocks are halved in j to double
// CTAs/SM: grid (B*32, 4, 2) = 1024 blocks x 128 threads, still one wave
// (9 CTAs/SM slots at 54 regs), occupancy ~2x for the MUFU/SHFL-latency loop.
__global__ __launch_bounds__(128) void voxel_kernel(
    const float* __restrict__ dv,     // (B, A, N, 3)
    const int*   __restrict__ an,     // (A, N) int32
    const float* __restrict__ sigma,  // (1,)
    float* __restrict__ out)          // (B, A, G, G, G)
{
    const int ba = blockIdx.x;        // b*32 + a
    const int a  = ba & 31;
    const int iq = blockIdx.y;        // slices [iq*8, iq*8+8)
    const int jh = blockIdx.z;        // j half: [jh*16, jh*16+16)
    const int t  = threadIdx.x;       // 0..127
    const int j  = (t >> 3) + (jh << 4);
    const int k0 = (t & 7) << 2;
    const int lane = t & 31;

    // One parallel round trip: sigma, an, and dv all issued together.
    const float sg = __ldg(sigma);
    bool act = false;
    float dxl = 0.f, dyl = 0.f, dzl = 0.f;
    if (lane < NN) {
        const float* p = dv + (ba * NN + lane) * 3;
        dxl = p[0];
        dyl = p[1];
        dzl = p[2];
        act = (an[a * NN + lane] == ATOM_TYPE);
    }
    unsigned mask = __ballot_sync(0xffffffffu, act);

    const float step = 8.0f / 31.0f;
    const float c2 = (-0.5f / (sg * sg)) * 1.4426950408889634f;  // coeff * log2(e)
    const float q  = ex2(2.0f * c2 * step * step);               // hoisted constant

    const float ti0 = -4.0f + (float)(iq * SLICES) * step;
    const float tj  = -4.0f + (float)j * step;
    const float tk0 = -4.0f + (float)k0 * step;

    float4 acc[SLICES];
    #pragma unroll
    for (int ii = 0; ii < SLICES; ++ii) acc[ii] = make_float4(0.f, 0.f, 0.f, 0.f);

    while (mask) {
        const int n = __ffs(mask) - 1;
        mask &= mask - 1;

        // Neighbor displacement via register-file broadcast (no memory).
        const float dx = __shfl_sync(0xffffffffu, dxl, n);
        const float dy = __shfl_sync(0xffffffffu, dyl, n);
        const float dz = __shfl_sync(0xffffffffu, dzl, n);

        const float ddx = ti0 - dx;
        const float ddy = tj  - dy;
        const float ddz = tk0 - dz;

        // Seeds: base value at (i0, j, k0) and first-step ratios along z and x.
        const float argb = c2 * (ddx * ddx + ddy * ddy + ddz * ddz);
        const float e0 = ex2(argb);
        float rz = ex2(c2 * fmaf(2.0f * ddz, step, step * step));
        float rx = ex2(c2 * fmaf(2.0f * ddx, step, step * step));

        // z-row at slice i0 via ratio walk (4 values).
        const float v0 = e0;
        const float v1 = v0 * rz;  rz *= q;
        const float v2 = v1 * rz;  rz *= q;
        const float v3 = v2 * rz;

        // x multipliers X1..X7 via ratio walk; X0 = 1.
        float xm[SLICES];
        xm[0] = 1.0f;
        xm[1] = rx;
        #pragma unroll
        for (int ii = 2; ii < SLICES; ++ii) {
            rx *= q;
            xm[ii] = xm[ii - 1] * rx;
        }

        acc[0].x += v0;  acc[0].y += v1;  acc[0].z += v2;  acc[0].w += v3;
        #pragma unroll
        for (int ii = 1; ii < SLICES; ++ii) {
            acc[ii].x = fmaf(xm[ii], v0, acc[ii].x);
            acc[ii].y = fmaf(xm[ii], v1, acc[ii].y);
            acc[ii].z = fmaf(xm[ii], v2, acc[ii].z);
            acc[ii].w = fmaf(xm[ii], v3, acc[ii].w);
        }
    }

    // j*GS + k0 == 4*t + 512*jh for t in [0,128).
    float* outp = out + ba * (GS * GS * GS)
                      + (iq * SLICES) * (GS * GS)
                      + (jh << 9) + 4 * t;
    #pragma unroll
    for (int ii = 0; ii < SLICES; ++ii)
        stg_cs(outp + ii * (GS * GS), acc[ii]);
}

extern "C" void kernel_launch(void* const* d_in, const int* in_sizes, int n_in,
                              void* d_out, int out_size) {
    const float* dv    = (const float*)d_in[0];   // distance_vector (B,32,16,3)
    const int*   an    = (const int*)d_in[1];     // atomic_numbers (32,16) int32
    const float* sigma = (const float*)d_in[2];   // (1,)
    float* out = (float*)d_out;

    const int B = in_sizes[0] / (32 * 16 * 3);    // derive batch from input size
    dim3 grid(B * 32, GS / SLICES, 2);            // (128, 4, 2) = 1024 blocks
    voxel_kernel<<<grid, 128>>>(dv, an, sigma, out);
}

// round 16
// speedup vs baseline: 1.0333x; 1.0333x over previous
#include <cuda_runtime.h>
#include <cuda_bf16.h>

#define GS 32
#define NN 16
#define SLICES 8
#define ATOM_TYPE 6

// Single MUFU EX2 regardless of compile flags.
__device__ __forceinline__ float ex2(float x) {
    float r;
    asm("ex2.approx.ftz.f32 %0, %1;" : "=f"(r) : "f"(x));
    return r;
}

// Streaming 128-bit store (evict-first: output is write-once).
__device__ __forceinline__ void stg_cs(float* p, float4 v) {
    asm volatile("st.global.cs.v4.f32 [%0], {%1,%2,%3,%4};"
                 :: "l"(p), "f"(v.x), "f"(v.y), "f"(v.z), "f"(v.w));
}

// out[b,a,i,j,k] = sum_{n: an[a,n]==6} exp(c*||grid - dv||^2), c = -0.5/sigma^2.
// CHAMPION (R14, twice validated at 6.62-6.66us kernel / 8.67-8.70us dur):
//  - Separable Gaussian on a uniform grid => geometric ratio recurrence:
//      e(g+1) = e(g)*r(g), r(g+1) = r(g)*q, q = exp2(2*c2*step^2) const.
//    3 ex2 seeds + ratio walks generate all 32 outputs of a thread.
//  - dv rows live in the register file (lane l holds row l); the mask loop
//    broadcasts them via shfl -> the loop contains NO memory operations.
//  - Block start is ONE parallel memory round trip (sigma + an + dv together).
//  - Register-only, barrier-free; block = (ba, 8 i-slices), 256 threads,
//    grid (B*32, 4) = 512 blocks -> single wave; natural register allocation
//    (both launch_bounds clamps regressed; kernel is ramp-limited, not
//    slot-limited -- measured occupancy is set by CTA delivery rate).
__global__ __launch_bounds__(256) void voxel_kernel(
    const float* __restrict__ dv,     // (B, A, N, 3)
    const int*   __restrict__ an,     // (A, N) int32
    const float* __restrict__ sigma,  // (1,)
    float* __restrict__ out)          // (B, A, G, G, G)
{
    const int ba = blockIdx.x;        // b*32 + a
    const int a  = ba & 31;
    const int iq = blockIdx.y;        // slices [iq*8, iq*8+8)
    const int t  = threadIdx.x;
    const int j  = t >> 3;
    const int k0 = (t & 7) << 2;
    const int lane = t & 31;

    // One parallel round trip: sigma, an, and dv all issued together.
    const float sg = __ldg(sigma);
    bool act = false;
    float dxl = 0.f, dyl = 0.f, dzl = 0.f;
    if (lane < NN) {
        const float* p = dv + (ba * NN + lane) * 3;
        dxl = p[0];
        dyl = p[1];
        dzl = p[2];
        act = (an[a * NN + lane] == ATOM_TYPE);
    }
    unsigned mask = __ballot_sync(0xffffffffu, act);

    const float step = 8.0f / 31.0f;
    const float c2 = (-0.5f / (sg * sg)) * 1.4426950408889634f;  // coeff * log2(e)
    const float q  = ex2(2.0f * c2 * step * step);               // hoisted constant

    const float ti0 = -4.0f + (float)(iq * SLICES) * step;
    const float tj  = -4.0f + (float)j * step;
    const float tk0 = -4.0f + (float)k0 * step;

    float4 acc[SLICES];
    #pragma unroll
    for (int ii = 0; ii < SLICES; ++ii) acc[ii] = make_float4(0.f, 0.f, 0.f, 0.f);

    while (mask) {
        const int n = __ffs(mask) - 1;
        mask &= mask - 1;

        // Neighbor displacement via register-file broadcast (no memory).
        const float dx = __shfl_sync(0xffffffffu, dxl, n);
        const float dy = __shfl_sync(0xffffffffu, dyl, n);
        const float dz = __shfl_sync(0xffffffffu, dzl, n);

        const float ddx = ti0 - dx;
        const float ddy = tj  - dy;
        const float ddz = tk0 - dz;

        // Seeds: base value at (i0, j, k0) and first-step ratios along z and x.
        const float argb = c2 * (ddx * ddx + ddy * ddy + ddz * ddz);
        const float e0 = ex2(argb);
        float rz = ex2(c2 * fmaf(2.0f * ddz, step, step * step));
        float rx = ex2(c2 * fmaf(2.0f * ddx, step, step * step));

        // z-row at slice i0 via ratio walk (4 values).
        const float v0 = e0;
        const float v1 = v0 * rz;  rz *= q;
        const float v2 = v1 * rz;  rz *= q;
        const float v3 = v2 * rz;

        // x multipliers X1..X7 via ratio walk; X0 = 1.
        float xm[SLICES];
        xm[0] = 1.0f;
        xm[1] = rx;
        #pragma unroll
        for (int ii = 2; ii < SLICES; ++ii) {
            rx *= q;
            xm[ii] = xm[ii - 1] * rx;
        }

        acc[0].x += v0;  acc[0].y += v1;  acc[0].z += v2;  acc[0].w += v3;
        #pragma unroll
        for (int ii = 1; ii < SLICES; ++ii) {
            acc[ii].x = fmaf(xm[ii], v0, acc[ii].x);
            acc[ii].y = fmaf(xm[ii], v1, acc[ii].y);
            acc[ii].z = fmaf(xm[ii], v2, acc[ii].z);
            acc[ii].w = fmaf(xm[ii], v3, acc[ii].w);
        }
    }

    float* outp = out + ba * (GS * GS * GS)
                      + (iq * SLICES) * (GS * GS)
                      + 4 * t;   // j*32 + k0 == 4*t
    #pragma unroll
    for (int ii = 0; ii < SLICES; ++ii)
        stg_cs(outp + ii * (GS * GS), acc[ii]);
}

extern "C" void kernel_launch(void* const* d_in, const int* in_sizes, int n_in,
                              void* d_out, int out_size) {
    const float* dv    = (const float*)d_in[0];   // distance_vector (B,32,16,3)
    const int*   an    = (const int*)d_in[1];     // atomic_numbers (32,16) int32
    const float* sigma = (const float*)d_in[2];   // (1,)
    float* out = (float*)d_out;

    const int B = in_sizes[0] / (32 * 16 * 3);    // derive batch from input size
    dim3 grid(B * 32, GS / SLICES);               // (128, 4) = 512 blocks
    voxel_kernel<<<grid, 256>>>(dv, an, sigma, out);
}